// round 10
// baseline (speedup 1.0000x reference)
#include <cuda_runtime.h>
#include <cuda_fp16.h>
#include <math.h>
#include <stdint.h>

#define BB   4
#define SS   2048
#define DD   1024
#define HH   16
#define HD   64
#define DFF  4096
#define ROWS (BB*SS)   // 8192
#define QST  (3*DD)    // qkv row stride

// ---------------- scratch (static device globals; no allocation) -----------
__device__ __half g_h   [ (size_t)ROWS*DD ];
__device__ __half g_qkv [ (size_t)ROWS*QST ];
__device__ __half g_ctx [ (size_t)ROWS*DD ];
__device__ float  g_x1  [ (size_t)ROWS*DD ];
__device__ __half g_ff  [ (size_t)ROWS*DFF ];
__device__ __half g_wqkv[ (size_t)DD*QST ];
__device__ __half g_wo  [ (size_t)DD*DD ];
__device__ __half g_w1  [ (size_t)DD*DFF ];
__device__ __half g_w2  [ (size_t)DFF*DD ];

// ======================= helpers ============================================
__device__ __forceinline__ uint32_t smem_u32(const void* p) {
    uint32_t a;
    asm("{ .reg .u64 t; cvta.to.shared.u64 t, %1; cvt.u32.u64 %0, t; }" : "=r"(a) : "l"(p));
    return a;
}
__device__ __forceinline__ void cp_async16(uint32_t dst, const void* src) {
    asm volatile("cp.async.cg.shared.global [%0], [%1], 16;" :: "r"(dst), "l"(src));
}
#define CP_COMMIT() asm volatile("cp.async.commit_group;")
#define CP_WAIT(N)  asm volatile("cp.async.wait_group %0;" :: "n"(N))

#define LDSM_X4(r0,r1,r2,r3, addr) \
    asm volatile("ldmatrix.sync.aligned.m8n8.x4.shared.b16 {%0,%1,%2,%3}, [%4];" \
        : "=r"(r0),"=r"(r1),"=r"(r2),"=r"(r3) : "r"(addr))
#define LDSM_X4T(r0,r1,r2,r3, addr) \
    asm volatile("ldmatrix.sync.aligned.m8n8.x4.trans.shared.b16 {%0,%1,%2,%3}, [%4];" \
        : "=r"(r0),"=r"(r1),"=r"(r2),"=r"(r3) : "r"(addr))

#define MMA_F16(acc, a0,a1,a2,a3, b0,b1) \
    asm volatile("mma.sync.aligned.m16n8k16.row.col.f32.f16.f16.f32 " \
        "{%0,%1,%2,%3}, {%4,%5,%6,%7}, {%8,%9}, {%0,%1,%2,%3};" \
        : "+f"((acc)[0]), "+f"((acc)[1]), "+f"((acc)[2]), "+f"((acc)[3]) \
        : "r"(a0), "r"(a1), "r"(a2), "r"(a3), "r"(b0), "r"(b1))

#define CVT_H2(d, hi, lo) \
    asm("cvt.rn.f16x2.f32 %0, %1, %2;" : "=r"(d) : "f"(hi), "f"(lo))
#define EX2_H2(d, a) \
    asm("ex2.approx.f16x2 %0, %1;" : "=r"(d) : "r"(a))

__device__ __forceinline__ float exp2_fast(float x) {
    float y;
    asm("ex2.approx.f32 %0, %1;" : "=f"(y) : "f"(x));
    return y;
}
__device__ __forceinline__ float tanh_fast(float x) {
    float y;
    asm("tanh.approx.f32 %0, %1;" : "=f"(y) : "f"(x));
    return y;
}
__device__ __forceinline__ float gelu_f(float x) {
    float u = 0.7978845608028654f * (x + 0.044715f * x * x * x);
    return 0.5f * x * (1.0f + tanh_fast(u));
}

// ========== fused: LN1 (blocks [0,ROWS)) + weight cvt (rest) ================
#define SEG (DD*DD/2)
#define SEGF (DD*DFF/2)
#define CVT_BLOCKS ((4*SEG + 2*SEGF)/256)    // 24576

__device__ __forceinline__ void ln_body(const float* __restrict__ xr,
                                        const float* __restrict__ scale,
                                        const float* __restrict__ shift,
                                        __half* __restrict__ orow)
{
    int t = threadIdx.x, wid = t >> 5, lane = t & 31;
    float v0 = xr[t], v1 = xr[t+256], v2 = xr[t+512], v3 = xr[t+768];
    float s  = v0+v1+v2+v3;
    float sq = v0*v0+v1*v1+v2*v2+v3*v3;
    #pragma unroll
    for (int off = 16; off > 0; off >>= 1) {
        s  += __shfl_xor_sync(0xffffffff, s,  off);
        sq += __shfl_xor_sync(0xffffffff, sq, off);
    }
    __shared__ float ws[2][8];
    if (lane == 0) { ws[0][wid] = s; ws[1][wid] = sq; }
    __syncthreads();
    float ts = 0.f, tsq = 0.f;
    #pragma unroll
    for (int i = 0; i < 8; i++) { ts += ws[0][i]; tsq += ws[1][i]; }
    float mean = ts * (1.0f/DD);
    float var  = tsq * (1.0f/DD) - mean*mean;
    float inv  = rsqrtf(var + 1e-8f);
    orow[t    ] = __float2half_rn(scale[t    ]*(v0-mean)*inv + shift[t    ]);
    orow[t+256] = __float2half_rn(scale[t+256]*(v1-mean)*inv + shift[t+256]);
    orow[t+512] = __float2half_rn(scale[t+512]*(v2-mean)*inv + shift[t+512]);
    orow[t+768] = __float2half_rn(scale[t+768]*(v3-mean)*inv + shift[t+768]);
}

__global__ __launch_bounds__(256)
void ln1_cvt_kernel(const float* __restrict__ x,
                    const float* __restrict__ ln1s, const float* __restrict__ ln1b,
                    __half* __restrict__ h,
                    const float* __restrict__ Wq, const float* __restrict__ Wk,
                    const float* __restrict__ Wv, const float* __restrict__ Wo,
                    const float* __restrict__ W1, const float* __restrict__ W2,
                    __half* __restrict__ wqkv, __half* __restrict__ wo,
                    __half* __restrict__ w1,   __half* __restrict__ w2)
{
    int bid = blockIdx.x;
    if (bid < ROWS) {
        ln_body(x + (size_t)bid * DD, ln1s, ln1b, h + (size_t)bid * DD);
        return;
    }
    int i = (bid - ROWS) * 256 + threadIdx.x;
    const float2* src;
    __half2* dst;
    if (i < 3*SEG) {
        int s = i / SEG, j = i - s * SEG;
        src = (const float2*)(s == 0 ? Wq : s == 1 ? Wk : Wv) + j;
        int r = j / (DD/2), c = j - r * (DD/2);
        dst = (__half2*)wqkv + (size_t)r * (QST/2) + s * (DD/2) + c;
    } else if (i < 4*SEG) {
        int j = i - 3*SEG;
        src = (const float2*)Wo + j;  dst = (__half2*)wo + j;
    } else if (i < 4*SEG + SEGF) {
        int j = i - 4*SEG;
        src = (const float2*)W1 + j;  dst = (__half2*)w1 + j;
    } else {
        int j = i - 4*SEG - SEGF;
        src = (const float2*)W2 + j;  dst = (__half2*)w2 + j;
    }
    float2 v = *src;
    *dst = __floats2half2_rn(v.x, v.y);
}

// plain LN kernel (for LN2)
__global__ __launch_bounds__(256)
void ln_kernel(const float* __restrict__ x, const float* __restrict__ scale,
               const float* __restrict__ shift, __half* __restrict__ out)
{
    int row = blockIdx.x;
    ln_body(x + (size_t)row * DD, scale, shift, out + (size_t)row * DD);
}

// ===== fp16 mma GEMM, CTA tile 256x128, BK=32, 3-stage, warp tile 64x64 =====
// 256 threads = 8 warps (4m x 2n).
#define AS_H 40
#define BS_H 136
#define SA_BYTES (256*AS_H*2)            // 20480
#define SB_BYTES (32*BS_H*2)             // 8704
#define STG_BYTES (SA_BYTES+SB_BYTES)    // 29184
#define GEMM_SMEM (3*STG_BYTES)          // 87552

template<int EPI, int OUTH>
__global__ __launch_bounds__(256, 2)
void tgemm(const __half* __restrict__ A, const __half* __restrict__ W,
           const float* __restrict__ bias, const float* __restrict__ res,
           void* __restrict__ C, int N, int K)
{
    extern __shared__ char smem[];
    const uint32_t sb = smem_u32(smem);
    const int tid  = threadIdx.x;
    const int wid  = tid >> 5, lane = tid & 31;
    const int g    = lane >> 2, tg = lane & 3;
    const int wm   = (wid >> 1) * 64, wn = (wid & 1) * 64;
    const int brow = blockIdx.y * 256, bcol = blockIdx.x * 128;

    float acc[4][8][4];
    #pragma unroll
    for (int mi=0;mi<4;mi++)
        #pragma unroll
        for (int ni=0;ni<8;ni++)
            #pragma unroll
            for (int e=0;e<4;e++) acc[mi][ni][e]=0.f;

    auto stage = [&](int c, int buf) {
        uint32_t base = sb + buf * STG_BYTES;
        int k0 = c * 32;
        #pragma unroll
        for (int it = 0; it < 4; it++) {               // A: 256 rows x 32 halves
            int idx = it * 256 + tid;
            int row = idx >> 2, c8 = (idx & 3) * 8;
            cp_async16(base + (uint32_t)(row * AS_H + c8) * 2,
                       A + (size_t)(brow + row) * K + k0 + c8);
        }
        #pragma unroll
        for (int it = 0; it < 2; it++) {               // B: 32 rows x 128 halves
            int idx = it * 256 + tid;
            int row = idx >> 4, c8 = (idx & 15) * 8;
            cp_async16(base + SA_BYTES + (uint32_t)(row * BS_H + c8) * 2,
                       W + (size_t)(k0 + row) * N + bcol + c8);
        }
        CP_COMMIT();
    };

    const uint32_t aoff = (uint32_t)((wm + (lane & 15)) * AS_H + 8 * (lane >> 4)) * 2;
    const uint32_t boff = (uint32_t)(((lane & 7) + 8 * ((lane >> 3) & 1)) * BS_H
                                     + wn + 8 * (lane >> 4)) * 2;

    const int nch = K / 32;
    stage(0, 0);
    stage(1, 1);
    for (int c = 0; c < nch; c++) {
        if (c + 2 < nch)      { stage(c + 2, (c + 2) % 3); CP_WAIT(2); }
        else if (c + 1 < nch) { CP_WAIT(1); }
        else                  { CP_WAIT(0); }
        __syncthreads();
        uint32_t sbuf = sb + (c % 3) * STG_BYTES;

        #pragma unroll
        for (int kb = 0; kb < 32; kb += 16) {
            uint32_t a[4][4];
            #pragma unroll
            for (int mi = 0; mi < 4; mi++)
                LDSM_X4(a[mi][0], a[mi][1], a[mi][2], a[mi][3],
                        sbuf + aoff + (uint32_t)(mi * 16 * AS_H + kb) * 2);
            #pragma unroll
            for (int np = 0; np < 4; np++) {
                uint32_t t0,t1,t2,t3;
                LDSM_X4T(t0,t1,t2,t3,
                         sbuf + SA_BYTES + boff + (uint32_t)(kb * BS_H + np * 16) * 2);
                #pragma unroll
                for (int mi = 0; mi < 4; mi++) {
                    MMA_F16(acc[mi][2*np],   a[mi][0],a[mi][1],a[mi][2],a[mi][3], t0,t1);
                    MMA_F16(acc[mi][2*np+1], a[mi][0],a[mi][1],a[mi][2],a[mi][3], t2,t3);
                }
            }
        }
        __syncthreads();
    }

    #pragma unroll
    for (int mi = 0; mi < 4; mi++) {
        int r0 = brow + wm + mi * 16 + g;
        #pragma unroll
        for (int ni = 0; ni < 8; ni++) {
            int c = bcol + wn + ni * 8 + 2 * tg;
            float v0 = acc[mi][ni][0], v1 = acc[mi][ni][1];
            float v2 = acc[mi][ni][2], v3 = acc[mi][ni][3];
            if (EPI == 1) {
                float b0 = bias[c], b1 = bias[c+1];
                const float* R0 = res + (size_t)r0 * N + c;
                const float* R1 = res + (size_t)(r0+8) * N + c;
                v0 += b0 + R0[0]; v1 += b1 + R0[1];
                v2 += b0 + R1[0]; v3 += b1 + R1[1];
            }
            if (EPI == 2) {
                float b0 = bias[c], b1 = bias[c+1];
                v0 = gelu_f(v0 + b0); v1 = gelu_f(v1 + b1);
                v2 = gelu_f(v2 + b0); v3 = gelu_f(v3 + b1);
            }
            if (OUTH) {
                __half* Ch = (__half*)C;
                *(__half2*)(Ch + (size_t)r0 * N + c)     = __floats2half2_rn(v0, v1);
                *(__half2*)(Ch + (size_t)(r0+8) * N + c) = __floats2half2_rn(v2, v3);
            } else {
                float* Cf = (float*)C;
                *(float2*)(Cf + (size_t)r0 * N + c)     = make_float2(v0, v1);
                *(float2*)(Cf + (size_t)(r0+8) * N + c) = make_float2(v2, v3);
            }
        }
    }
}

// ============ fp16 tensor-core causal flash attention (R9, unchanged) =======
#define AQ_H 72
#define ATT_Q_OFF 0
#define ATT_K_OFF (128*AQ_H)
#define ATT_V_OFF (ATT_K_OFF + 2*64*AQ_H)
#define ATT_SMEM  ((ATT_V_OFF + 2*64*AQ_H)*2)   // 55296 bytes
#define SCL2 (0.125f * 1.44269504088896f)
#define ONES_H2 0x3C003C00u

__global__ __launch_bounds__(256, 2)
void attn_kernel(const __half* __restrict__ QKV, __half* __restrict__ O)
{
    extern __shared__ __half sh[];
    const uint32_t sb = smem_u32(sh);

    const int qt = blockIdx.x, bh = blockIdx.y;
    const int b = bh >> 4, hh = bh & 15;
    const int tid = threadIdx.x, w = tid >> 5, lane = tid & 31;
    const int g = lane >> 2, tg = lane & 3;

    {
        const __half* Qg = QKV + ((size_t)(b*SS + qt*128))*QST + hh*64;
        #pragma unroll
        for (int it = 0; it < 4; it++) {
            int idx = it * 256 + tid;
            int row = idx >> 3, c8 = (idx & 7) * 8;
            cp_async16(sb + (uint32_t)(ATT_Q_OFF + row * AQ_H + c8) * 2,
                       Qg + (size_t)row * QST + c8);
        }
    }
    auto loadKV = [&](int kt, int buf) {
        const __half* Kg = QKV + ((size_t)(b*SS + kt*64))*QST + DD   + hh*64;
        const __half* Vg = QKV + ((size_t)(b*SS + kt*64))*QST + 2*DD + hh*64;
        uint32_t kbase = sb + (uint32_t)(ATT_K_OFF + buf * 64 * AQ_H) * 2;
        uint32_t vbase = sb + (uint32_t)(ATT_V_OFF + buf * 64 * AQ_H) * 2;
        #pragma unroll
        for (int it = 0; it < 2; it++) {
            int idx = it * 256 + tid;
            int row = idx >> 3, c8 = (idx & 7) * 8;
            cp_async16(kbase + (uint32_t)(row * AQ_H + c8) * 2, Kg + (size_t)row * QST + c8);
            cp_async16(vbase + (uint32_t)(row * AQ_H + c8) * 2, Vg + (size_t)row * QST + c8);
        }
        CP_COMMIT();
    };

    float oacc[8][4];
    #pragma unroll
    for (int ni=0;ni<8;ni++)
        #pragma unroll
        for (int e=0;e<4;e++) oacc[ni][e]=0.f;
    float lacc[4] = {0.f, 0.f, 0.f, 0.f};
    float m0 = -INFINITY, m1 = -INFINITY;

    const uint32_t qoff = (uint32_t)((w*16 + (lane & 15)) * AQ_H + 8 * (lane >> 4)) * 2;
    const uint32_t koff = (uint32_t)(((lane & 7) + 8 * (lane >> 4)) * AQ_H
                                     + 8 * ((lane >> 3) & 1)) * 2;
    const uint32_t voff = (uint32_t)(((lane & 7) + 8 * ((lane >> 3) & 1)) * AQ_H
                                     + 8 * (lane >> 4)) * 2;

    loadKV(0, 0);
    const int nkt = 2 * qt + 2;
    for (int kt = 0; kt < nkt; kt++) {
        int buf = kt & 1;
        if (kt + 1 < nkt) { loadKV(kt + 1, buf ^ 1); CP_WAIT(1); }
        else              { CP_WAIT(0); }
        __syncthreads();

        uint32_t kb_sm = sb + (uint32_t)(ATT_K_OFF + buf * 64 * AQ_H) * 2;
        uint32_t vb_sm = sb + (uint32_t)(ATT_V_OFF + buf * 64 * AQ_H) * 2;

        float sacc[8][4];
        #pragma unroll
        for (int ni=0;ni<8;ni++)
            #pragma unroll
            for (int e=0;e<4;e++) sacc[ni][e]=0.f;

        #pragma unroll
        for (int kb = 0; kb < 64; kb += 16) {
            uint32_t a0,a1,a2,a3;
            LDSM_X4(a0,a1,a2,a3, sb + (uint32_t)(ATT_Q_OFF)*2 + qoff + (uint32_t)kb * 2);
            #pragma unroll
            for (int np = 0; np < 4; np++) {
                uint32_t t0,t1,t2,t3;
                LDSM_X4(t0,t1,t2,t3, kb_sm + koff + (uint32_t)(np * 16 * AQ_H + kb) * 2);
                MMA_F16(sacc[2*np],   a0,a1,a2,a3, t0,t1);
                MMA_F16(sacc[2*np+1], a0,a1,a2,a3, t2,t3);
            }
        }

        const bool needMask = (kt * 64 + 63) > (qt*128 + w*16);
        if (needMask) {
            const int qg0 = qt*128 + w*16 + g, qg1 = qg0 + 8;
            #pragma unroll
            for (int ni = 0; ni < 8; ni++) {
                int key0 = kt*64 + ni*8 + 2*tg;
                #pragma unroll
                for (int e = 0; e < 4; e++) {
                    int key = key0 + (e & 1);
                    int qr  = (e >= 2) ? qg1 : qg0;
                    if (key > qr) sacc[ni][e] = -INFINITY;
                }
            }
        }

        float rx0 = -INFINITY, rx1 = -INFINITY;
        #pragma unroll
        for (int ni = 0; ni < 8; ni++) {
            rx0 = fmaxf(rx0, fmaxf(sacc[ni][0], sacc[ni][1]));
            rx1 = fmaxf(rx1, fmaxf(sacc[ni][2], sacc[ni][3]));
        }
        rx0 = fmaxf(rx0, __shfl_xor_sync(0xffffffff, rx0, 1));
        rx0 = fmaxf(rx0, __shfl_xor_sync(0xffffffff, rx0, 2));
        rx1 = fmaxf(rx1, __shfl_xor_sync(0xffffffff, rx1, 1));
        rx1 = fmaxf(rx1, __shfl_xor_sync(0xffffffff, rx1, 2));
        float mn0 = fmaxf(m0, rx0 * SCL2), mn1 = fmaxf(m1, rx1 * SCL2);
        float c0 = exp2_fast(m0 - mn0), c1 = exp2_fast(m1 - mn1);
        float nm0 = -mn0, nm1 = -mn1;
        m0 = mn0;  m1 = mn1;

        uint32_t aP[4][4];
        #pragma unroll
        for (int j = 0; j < 4; j++) {
            int n0 = 2*j, n1 = 2*j + 1;
            float d00 = fmaf(sacc[n0][0], SCL2, nm0);
            float d01 = fmaf(sacc[n0][1], SCL2, nm0);
            float d02 = fmaf(sacc[n0][2], SCL2, nm1);
            float d03 = fmaf(sacc[n0][3], SCL2, nm1);
            float d10 = fmaf(sacc[n1][0], SCL2, nm0);
            float d11 = fmaf(sacc[n1][1], SCL2, nm0);
            float d12 = fmaf(sacc[n1][2], SCL2, nm1);
            float d13 = fmaf(sacc[n1][3], SCL2, nm1);
            uint32_t u0, u1, u2, u3;
            CVT_H2(u0, d01, d00);
            CVT_H2(u1, d03, d02);
            CVT_H2(u2, d11, d10);
            CVT_H2(u3, d13, d12);
            EX2_H2(aP[j][0], u0);
            EX2_H2(aP[j][1], u1);
            EX2_H2(aP[j][2], u2);
            EX2_H2(aP[j][3], u3);
        }

        #pragma unroll
        for (int ni = 0; ni < 8; ni++) {
            oacc[ni][0] *= c0; oacc[ni][1] *= c0;
            oacc[ni][2] *= c1; oacc[ni][3] *= c1;
        }
        lacc[0] *= c0; lacc[1] *= c0; lacc[2] *= c1; lacc[3] *= c1;

        #pragma unroll
        for (int j = 0; j < 4; j++)
            MMA_F16(lacc, aP[j][0],aP[j][1],aP[j][2],aP[j][3], ONES_H2, ONES_H2);

        #pragma unroll
        for (int j = 0; j < 4; j++) {
            #pragma unroll
            for (int np = 0; np < 4; np++) {
                uint32_t t0,t1,t2,t3;
                LDSM_X4T(t0,t1,t2,t3, vb_sm + voff + (uint32_t)(j * 16 * AQ_H + np * 16) * 2);
                MMA_F16(oacc[2*np],   aP[j][0],aP[j][1],aP[j][2],aP[j][3], t0,t1);
                MMA_F16(oacc[2*np+1], aP[j][0],aP[j][1],aP[j][2],aP[j][3], t2,t3);
            }
        }
        __syncthreads();
    }

    float i0 = 1.f / lacc[0], i1 = 1.f / lacc[2];
    #pragma unroll
    for (int ni = 0; ni < 8; ni++) {
        int c = hh*64 + ni*8 + 2*tg;
        size_t go = ((size_t)(b*SS + qt*128 + w*16 + g)) * DD + c;
        *(__half2*)(O + go)        = __floats2half2_rn(oacc[ni][0]*i0, oacc[ni][1]*i0);
        *(__half2*)(O + go + 8*DD) = __floats2half2_rn(oacc[ni][2]*i1, oacc[ni][3]*i1);
    }
}

// ======================= launcher ===========================================
extern "C" void kernel_launch(void* const* d_in, const int* in_sizes, int n_in,
                              void* d_out, int out_size)
{
    const float* x    = (const float*)d_in[0];
    const float* Wq   = (const float*)d_in[1];
    const float* Wk   = (const float*)d_in[2];
    const float* Wv   = (const float*)d_in[3];
    const float* Wo   = (const float*)d_in[4];
    const float* bo   = (const float*)d_in[5];
    const float* W1   = (const float*)d_in[6];
    const float* b1   = (const float*)d_in[7];
    const float* W2   = (const float*)d_in[8];
    const float* b2   = (const float*)d_in[9];
    const float* ln1s = (const float*)d_in[10];
    const float* ln1b = (const float*)d_in[11];
    const float* ln2s = (const float*)d_in[12];
    const float* ln2b = (const float*)d_in[13];
    float* out = (float*)d_out;

    __half *h,*qkv,*ctx,*ff,*wqkv,*wo,*w1,*w2;
    float *x1;
    cudaGetSymbolAddress((void**)&h,    g_h);
    cudaGetSymbolAddress((void**)&qkv,  g_qkv);
    cudaGetSymbolAddress((void**)&ctx,  g_ctx);
    cudaGetSymbolAddress((void**)&x1,   g_x1);
    cudaGetSymbolAddress((void**)&ff,   g_ff);
    cudaGetSymbolAddress((void**)&wqkv, g_wqkv);
    cudaGetSymbolAddress((void**)&wo,   g_wo);
    cudaGetSymbolAddress((void**)&w1,   g_w1);
    cudaGetSymbolAddress((void**)&w2,   g_w2);

    cudaFuncSetAttribute(tgemm<0,1>, cudaFuncAttributeMaxDynamicSharedMemorySize, GEMM_SMEM);
    cudaFuncSetAttribute(tgemm<1,0>, cudaFuncAttributeMaxDynamicSharedMemorySize, GEMM_SMEM);
    cudaFuncSetAttribute(tgemm<2,1>, cudaFuncAttributeMaxDynamicSharedMemorySize, GEMM_SMEM);
    cudaFuncSetAttribute(attn_kernel, cudaFuncAttributeMaxDynamicSharedMemorySize, ATT_SMEM);

    // fused LN1 + weight conversion (independent work, one launch)
    ln1_cvt_kernel<<<ROWS + CVT_BLOCKS, 256>>>(x, ln1s, ln1b, h,
                                               Wq, Wk, Wv, Wo, W1, W2,
                                               wqkv, wo, w1, w2);

    dim3 gQKV(QST/128, ROWS/256);  // (24, 32)
    dim3 gD  (DD/128,  ROWS/256);  // (8, 32)
    dim3 gFF (DFF/128, ROWS/256);  // (32, 32)

    tgemm<0,1><<<gQKV, 256, GEMM_SMEM>>>(h, wqkv, nullptr, nullptr, qkv, QST, DD);
    attn_kernel<<<dim3(SS/128, BB*HH), 256, ATT_SMEM>>>(qkv, ctx);
    tgemm<1,0><<<gD, 256, GEMM_SMEM>>>(ctx, wo, bo, x, x1, DD, DD);
    ln_kernel<<<ROWS, 256>>>(x1, ln2s, ln2b, h);
    tgemm<2,1><<<gFF, 256, GEMM_SMEM>>>(h, w1, b1, nullptr, ff, DFF, DD);
    tgemm<1,0><<<gD, 256, GEMM_SMEM>>>(ff, w2, b2, x1, out, DD, DFF);
}

// round 11
// speedup vs baseline: 2.1397x; 2.1397x over previous
#include <cuda_runtime.h>
#include <cuda_fp16.h>
#include <math.h>
#include <stdint.h>

#define BB   4
#define SS   2048
#define DD   1024
#define HH   16
#define HD   64
#define DFF  4096
#define ROWS (BB*SS)   // 8192
#define QST  (3*DD)    // qkv row stride

// ---------------- scratch (static device globals; no allocation) -----------
__device__ __half g_h   [ (size_t)ROWS*DD ];
__device__ __half g_qkv [ (size_t)ROWS*QST ];
__device__ __half g_ctx [ (size_t)ROWS*DD ];
__device__ float  g_x1  [ (size_t)ROWS*DD ];
__device__ __half g_ff  [ (size_t)ROWS*DFF ];
__device__ __half g_wqkv[ (size_t)DD*QST ];
__device__ __half g_wo  [ (size_t)DD*DD ];
__device__ __half g_w1  [ (size_t)DD*DFF ];
__device__ __half g_w2  [ (size_t)DFF*DD ];

// ======================= helpers ============================================
__device__ __forceinline__ uint32_t smem_u32(const void* p) {
    uint32_t a;
    asm("{ .reg .u64 t; cvta.to.shared.u64 t, %1; cvt.u32.u64 %0, t; }" : "=r"(a) : "l"(p));
    return a;
}
__device__ __forceinline__ void cp_async16(uint32_t dst, const void* src) {
    asm volatile("cp.async.cg.shared.global [%0], [%1], 16;" :: "r"(dst), "l"(src));
}
#define CP_COMMIT() asm volatile("cp.async.commit_group;")
#define CP_WAIT(N)  asm volatile("cp.async.wait_group %0;" :: "n"(N))

#define LDSM_X4(r0,r1,r2,r3, addr) \
    asm volatile("ldmatrix.sync.aligned.m8n8.x4.shared.b16 {%0,%1,%2,%3}, [%4];" \
        : "=r"(r0),"=r"(r1),"=r"(r2),"=r"(r3) : "r"(addr))
#define LDSM_X4T(r0,r1,r2,r3, addr) \
    asm volatile("ldmatrix.sync.aligned.m8n8.x4.trans.shared.b16 {%0,%1,%2,%3}, [%4];" \
        : "=r"(r0),"=r"(r1),"=r"(r2),"=r"(r3) : "r"(addr))

#define MMA_F16(acc, a0,a1,a2,a3, b0,b1) \
    asm volatile("mma.sync.aligned.m16n8k16.row.col.f32.f16.f16.f32 " \
        "{%0,%1,%2,%3}, {%4,%5,%6,%7}, {%8,%9}, {%0,%1,%2,%3};" \
        : "+f"((acc)[0]), "+f"((acc)[1]), "+f"((acc)[2]), "+f"((acc)[3]) \
        : "r"(a0), "r"(a1), "r"(a2), "r"(a3), "r"(b0), "r"(b1))

#define CVT_H2(d, hi, lo) \
    asm("cvt.rn.f16x2.f32 %0, %1, %2;" : "=r"(d) : "f"(hi), "f"(lo))
#define EX2_H2(d, a) \
    asm("ex2.approx.f16x2 %0, %1;" : "=r"(d) : "r"(a))

__device__ __forceinline__ float exp2_fast(float x) {
    float y;
    asm("ex2.approx.f32 %0, %1;" : "=f"(y) : "f"(x));
    return y;
}
__device__ __forceinline__ float tanh_fast(float x) {
    float y;
    asm("tanh.approx.f32 %0, %1;" : "=f"(y) : "f"(x));
    return y;
}
__device__ __forceinline__ float gelu_f(float x) {
    float u = 0.7978845608028654f * (x + 0.044715f * x * x * x);
    return 0.5f * x * (1.0f + tanh_fast(u));
}

// ========== fused: LN1 (blocks [0,ROWS)) + weight cvt (rest) ================
#define SEG (DD*DD/2)
#define SEGF (DD*DFF/2)
#define CVT_BLOCKS ((4*SEG + 2*SEGF)/256)    // 24576

__device__ __forceinline__ void ln_body(const float* __restrict__ xr,
                                        const float* __restrict__ scale,
                                        const float* __restrict__ shift,
                                        __half* __restrict__ orow)
{
    int t = threadIdx.x, wid = t >> 5, lane = t & 31;
    float v0 = xr[t], v1 = xr[t+256], v2 = xr[t+512], v3 = xr[t+768];
    float s  = v0+v1+v2+v3;
    float sq = v0*v0+v1*v1+v2*v2+v3*v3;
    #pragma unroll
    for (int off = 16; off > 0; off >>= 1) {
        s  += __shfl_xor_sync(0xffffffff, s,  off);
        sq += __shfl_xor_sync(0xffffffff, sq, off);
    }
    __shared__ float ws[2][8];
    if (lane == 0) { ws[0][wid] = s; ws[1][wid] = sq; }
    __syncthreads();
    float ts = 0.f, tsq = 0.f;
    #pragma unroll
    for (int i = 0; i < 8; i++) { ts += ws[0][i]; tsq += ws[1][i]; }
    float mean = ts * (1.0f/DD);
    float var  = tsq * (1.0f/DD) - mean*mean;
    float inv  = rsqrtf(var + 1e-8f);
    orow[t    ] = __float2half_rn(scale[t    ]*(v0-mean)*inv + shift[t    ]);
    orow[t+256] = __float2half_rn(scale[t+256]*(v1-mean)*inv + shift[t+256]);
    orow[t+512] = __float2half_rn(scale[t+512]*(v2-mean)*inv + shift[t+512]);
    orow[t+768] = __float2half_rn(scale[t+768]*(v3-mean)*inv + shift[t+768]);
}

__global__ __launch_bounds__(256)
void ln1_cvt_kernel(const float* __restrict__ x,
                    const float* __restrict__ ln1s, const float* __restrict__ ln1b,
                    __half* __restrict__ h,
                    const float* __restrict__ Wq, const float* __restrict__ Wk,
                    const float* __restrict__ Wv, const float* __restrict__ Wo,
                    const float* __restrict__ W1, const float* __restrict__ W2,
                    __half* __restrict__ wqkv, __half* __restrict__ wo,
                    __half* __restrict__ w1,   __half* __restrict__ w2)
{
    int bid = blockIdx.x;
    if (bid < ROWS) {
        ln_body(x + (size_t)bid * DD, ln1s, ln1b, h + (size_t)bid * DD);
        return;
    }
    int i = (bid - ROWS) * 256 + threadIdx.x;
    const float2* src;
    __half2* dst;
    if (i < 3*SEG) {
        int s = i / SEG, j = i - s * SEG;
        src = (const float2*)(s == 0 ? Wq : s == 1 ? Wk : Wv) + j;
        int r = j / (DD/2), c = j - r * (DD/2);
        dst = (__half2*)wqkv + (size_t)r * (QST/2) + s * (DD/2) + c;
    } else if (i < 4*SEG) {
        int j = i - 3*SEG;
        src = (const float2*)Wo + j;  dst = (__half2*)wo + j;
    } else if (i < 4*SEG + SEGF) {
        int j = i - 4*SEG;
        src = (const float2*)W1 + j;  dst = (__half2*)w1 + j;
    } else {
        int j = i - 4*SEG - SEGF;
        src = (const float2*)W2 + j;  dst = (__half2*)w2 + j;
    }
    float2 v = *src;
    *dst = __floats2half2_rn(v.x, v.y);
}

// plain LN kernel (for LN2)
__global__ __launch_bounds__(256)
void ln_kernel(const float* __restrict__ x, const float* __restrict__ scale,
               const float* __restrict__ shift, __half* __restrict__ out)
{
    int row = blockIdx.x;
    ln_body(x + (size_t)row * DD, scale, shift, out + (size_t)row * DD);
}

// ========== fp16 mma GEMM, BK=32, 3-stage cp.async, warp tile 64x64 =========
// (R9 configuration — measured best: 128 thr, 128x128 CTA tile, occupancy 2)
#define AS_H 40
#define BS_H 136
#define SA_BYTES (128*AS_H*2)
#define SB_BYTES (32*BS_H*2)
#define STG_BYTES (SA_BYTES+SB_BYTES)
#define GEMM_SMEM (3*STG_BYTES)          // 56832

template<int EPI, int OUTH>
__global__ __launch_bounds__(128, 2)
void tgemm(const __half* __restrict__ A, const __half* __restrict__ W,
           const float* __restrict__ bias, const float* __restrict__ res,
           void* __restrict__ C, int N, int K)
{
    extern __shared__ char smem[];
    const uint32_t sb = smem_u32(smem);
    const int tid  = threadIdx.x;
    const int wid  = tid >> 5, lane = tid & 31;
    const int g    = lane >> 2, tg = lane & 3;
    const int wm   = (wid >> 1) * 64, wn = (wid & 1) * 64;
    const int brow = blockIdx.y * 128, bcol = blockIdx.x * 128;

    float acc[4][8][4];
    #pragma unroll
    for (int mi=0;mi<4;mi++)
        #pragma unroll
        for (int ni=0;ni<8;ni++)
            #pragma unroll
            for (int e=0;e<4;e++) acc[mi][ni][e]=0.f;

    auto stage = [&](int c, int buf) {
        uint32_t base = sb + buf * STG_BYTES;
        int k0 = c * 32;
        #pragma unroll
        for (int it = 0; it < 4; it++) {
            int idx = it * 128 + tid;
            int row = idx >> 2, c8 = (idx & 3) * 8;
            cp_async16(base + (uint32_t)(row * AS_H + c8) * 2,
                       A + (size_t)(brow + row) * K + k0 + c8);
        }
        #pragma unroll
        for (int it = 0; it < 4; it++) {
            int idx = it * 128 + tid;
            int row = idx >> 4, c8 = (idx & 15) * 8;
            cp_async16(base + SA_BYTES + (uint32_t)(row * BS_H + c8) * 2,
                       W + (size_t)(k0 + row) * N + bcol + c8);
        }
        CP_COMMIT();
    };

    const uint32_t aoff = (uint32_t)((wm + (lane & 15)) * AS_H + 8 * (lane >> 4)) * 2;
    const uint32_t boff = (uint32_t)(((lane & 7) + 8 * ((lane >> 3) & 1)) * BS_H
                                     + wn + 8 * (lane >> 4)) * 2;

    const int nch = K / 32;
    stage(0, 0);
    stage(1, 1);
    for (int c = 0; c < nch; c++) {
        if (c + 2 < nch)      { stage(c + 2, (c + 2) % 3); CP_WAIT(2); }
        else if (c + 1 < nch) { CP_WAIT(1); }
        else                  { CP_WAIT(0); }
        __syncthreads();
        uint32_t sbuf = sb + (c % 3) * STG_BYTES;

        #pragma unroll
        for (int kb = 0; kb < 32; kb += 16) {
            uint32_t a[4][4];
            #pragma unroll
            for (int mi = 0; mi < 4; mi++)
                LDSM_X4(a[mi][0], a[mi][1], a[mi][2], a[mi][3],
                        sbuf + aoff + (uint32_t)(mi * 16 * AS_H + kb) * 2);
            #pragma unroll
            for (int np = 0; np < 4; np++) {
                uint32_t t0,t1,t2,t3;
                LDSM_X4T(t0,t1,t2,t3,
                         sbuf + SA_BYTES + boff + (uint32_t)(kb * BS_H + np * 16) * 2);
                #pragma unroll
                for (int mi = 0; mi < 4; mi++) {
                    MMA_F16(acc[mi][2*np],   a[mi][0],a[mi][1],a[mi][2],a[mi][3], t0,t1);
                    MMA_F16(acc[mi][2*np+1], a[mi][0],a[mi][1],a[mi][2],a[mi][3], t2,t3);
                }
            }
        }
        __syncthreads();
    }

    #pragma unroll
    for (int mi = 0; mi < 4; mi++) {
        int r0 = brow + wm + mi * 16 + g;
        #pragma unroll
        for (int ni = 0; ni < 8; ni++) {
            int c = bcol + wn + ni * 8 + 2 * tg;
            float v0 = acc[mi][ni][0], v1 = acc[mi][ni][1];
            float v2 = acc[mi][ni][2], v3 = acc[mi][ni][3];
            if (EPI == 1) {
                float b0 = bias[c], b1 = bias[c+1];
                const float* R0 = res + (size_t)r0 * N + c;
                const float* R1 = res + (size_t)(r0+8) * N + c;
                v0 += b0 + R0[0]; v1 += b1 + R0[1];
                v2 += b0 + R1[0]; v3 += b1 + R1[1];
            }
            if (EPI == 2) {
                float b0 = bias[c], b1 = bias[c+1];
                v0 = gelu_f(v0 + b0); v1 = gelu_f(v1 + b1);
                v2 = gelu_f(v2 + b0); v3 = gelu_f(v3 + b1);
            }
            if (OUTH) {
                __half* Ch = (__half*)C;
                *(__half2*)(Ch + (size_t)r0 * N + c)     = __floats2half2_rn(v0, v1);
                *(__half2*)(Ch + (size_t)(r0+8) * N + c) = __floats2half2_rn(v2, v3);
            } else {
                float* Cf = (float*)C;
                *(float2*)(Cf + (size_t)r0 * N + c)     = make_float2(v0, v1);
                *(float2*)(Cf + (size_t)(r0+8) * N + c) = make_float2(v2, v3);
            }
        }
    }
}

// ============ fp16 tensor-core causal flash attention (R9 + heavy-first) ====
#define AQ_H 72
#define ATT_Q_OFF 0
#define ATT_K_OFF (128*AQ_H)
#define ATT_V_OFF (ATT_K_OFF + 2*64*AQ_H)
#define ATT_SMEM  ((ATT_V_OFF + 2*64*AQ_H)*2)   // 55296 bytes
#define SCL2 (0.125f * 1.44269504088896f)
#define ONES_H2 0x3C003C00u

__global__ __launch_bounds__(256, 2)
void attn_kernel(const __half* __restrict__ QKV, __half* __restrict__ O)
{
    extern __shared__ __half sh[];
    const uint32_t sb = smem_u32(sh);

    // heavy blocks (large qt) scheduled first to shrink the tail wave
    const int qt = (int)gridDim.x - 1 - (int)blockIdx.x;
    const int bh = blockIdx.y;
    const int b = bh >> 4, hh = bh & 15;
    const int tid = threadIdx.x, w = tid >> 5, lane = tid & 31;
    const int g = lane >> 2, tg = lane & 3;

    {
        const __half* Qg = QKV + ((size_t)(b*SS + qt*128))*QST + hh*64;
        #pragma unroll
        for (int it = 0; it < 4; it++) {
            int idx = it * 256 + tid;
            int row = idx >> 3, c8 = (idx & 7) * 8;
            cp_async16(sb + (uint32_t)(ATT_Q_OFF + row * AQ_H + c8) * 2,
                       Qg + (size_t)row * QST + c8);
        }
    }
    auto loadKV = [&](int kt, int buf) {
        const __half* Kg = QKV + ((size_t)(b*SS + kt*64))*QST + DD   + hh*64;
        const __half* Vg = QKV + ((size_t)(b*SS + kt*64))*QST + 2*DD + hh*64;
        uint32_t kbase = sb + (uint32_t)(ATT_K_OFF + buf * 64 * AQ_H) * 2;
        uint32_t vbase = sb + (uint32_t)(ATT_V_OFF + buf * 64 * AQ_H) * 2;
        #pragma unroll
        for (int it = 0; it < 2; it++) {
            int idx = it * 256 + tid;
            int row = idx >> 3, c8 = (idx & 7) * 8;
            cp_async16(kbase + (uint32_t)(row * AQ_H + c8) * 2, Kg + (size_t)row * QST + c8);
            cp_async16(vbase + (uint32_t)(row * AQ_H + c8) * 2, Vg + (size_t)row * QST + c8);
        }
        CP_COMMIT();
    };

    float oacc[8][4];
    #pragma unroll
    for (int ni=0;ni<8;ni++)
        #pragma unroll
        for (int e=0;e<4;e++) oacc[ni][e]=0.f;
    float lacc[4] = {0.f, 0.f, 0.f, 0.f};
    float m0 = -INFINITY, m1 = -INFINITY;

    const uint32_t qoff = (uint32_t)((w*16 + (lane & 15)) * AQ_H + 8 * (lane >> 4)) * 2;
    const uint32_t koff = (uint32_t)(((lane & 7) + 8 * (lane >> 4)) * AQ_H
                                     + 8 * ((lane >> 3) & 1)) * 2;
    const uint32_t voff = (uint32_t)(((lane & 7) + 8 * ((lane >> 3) & 1)) * AQ_H
                                     + 8 * (lane >> 4)) * 2;

    loadKV(0, 0);
    const int nkt = 2 * qt + 2;
    for (int kt = 0; kt < nkt; kt++) {
        int buf = kt & 1;
        if (kt + 1 < nkt) { loadKV(kt + 1, buf ^ 1); CP_WAIT(1); }
        else              { CP_WAIT(0); }
        __syncthreads();

        uint32_t kb_sm = sb + (uint32_t)(ATT_K_OFF + buf * 64 * AQ_H) * 2;
        uint32_t vb_sm = sb + (uint32_t)(ATT_V_OFF + buf * 64 * AQ_H) * 2;

        float sacc[8][4];
        #pragma unroll
        for (int ni=0;ni<8;ni++)
            #pragma unroll
            for (int e=0;e<4;e++) sacc[ni][e]=0.f;

        #pragma unroll
        for (int kb = 0; kb < 64; kb += 16) {
            uint32_t a0,a1,a2,a3;
            LDSM_X4(a0,a1,a2,a3, sb + (uint32_t)(ATT_Q_OFF)*2 + qoff + (uint32_t)kb * 2);
            #pragma unroll
            for (int np = 0; np < 4; np++) {
                uint32_t t0,t1,t2,t3;
                LDSM_X4(t0,t1,t2,t3, kb_sm + koff + (uint32_t)(np * 16 * AQ_H + kb) * 2);
                MMA_F16(sacc[2*np],   a0,a1,a2,a3, t0,t1);
                MMA_F16(sacc[2*np+1], a0,a1,a2,a3, t2,t3);
            }
        }

        const bool needMask = (kt * 64 + 63) > (qt*128 + w*16);
        if (needMask) {
            const int qg0 = qt*128 + w*16 + g, qg1 = qg0 + 8;
            #pragma unroll
            for (int ni = 0; ni < 8; ni++) {
                int key0 = kt*64 + ni*8 + 2*tg;
                #pragma unroll
                for (int e = 0; e < 4; e++) {
                    int key = key0 + (e & 1);
                    int qr  = (e >= 2) ? qg1 : qg0;
                    if (key > qr) sacc[ni][e] = -INFINITY;
                }
            }
        }

        float rx0 = -INFINITY, rx1 = -INFINITY;
        #pragma unroll
        for (int ni = 0; ni < 8; ni++) {
            rx0 = fmaxf(rx0, fmaxf(sacc[ni][0], sacc[ni][1]));
            rx1 = fmaxf(rx1, fmaxf(sacc[ni][2], sacc[ni][3]));
        }
        rx0 = fmaxf(rx0, __shfl_xor_sync(0xffffffff, rx0, 1));
        rx0 = fmaxf(rx0, __shfl_xor_sync(0xffffffff, rx0, 2));
        rx1 = fmaxf(rx1, __shfl_xor_sync(0xffffffff, rx1, 1));
        rx1 = fmaxf(rx1, __shfl_xor_sync(0xffffffff, rx1, 2));
        float mn0 = fmaxf(m0, rx0 * SCL2), mn1 = fmaxf(m1, rx1 * SCL2);
        float c0 = exp2_fast(m0 - mn0), c1 = exp2_fast(m1 - mn1);
        float nm0 = -mn0, nm1 = -mn1;
        m0 = mn0;  m1 = mn1;

        uint32_t aP[4][4];
        #pragma unroll
        for (int j = 0; j < 4; j++) {
            int n0 = 2*j, n1 = 2*j + 1;
            float d00 = fmaf(sacc[n0][0], SCL2, nm0);
            float d01 = fmaf(sacc[n0][1], SCL2, nm0);
            float d02 = fmaf(sacc[n0][2], SCL2, nm1);
            float d03 = fmaf(sacc[n0][3], SCL2, nm1);
            float d10 = fmaf(sacc[n1][0], SCL2, nm0);
            float d11 = fmaf(sacc[n1][1], SCL2, nm0);
            float d12 = fmaf(sacc[n1][2], SCL2, nm1);
            float d13 = fmaf(sacc[n1][3], SCL2, nm1);
            uint32_t u0, u1, u2, u3;
            CVT_H2(u0, d01, d00);
            CVT_H2(u1, d03, d02);
            CVT_H2(u2, d11, d10);
            CVT_H2(u3, d13, d12);
            EX2_H2(aP[j][0], u0);
            EX2_H2(aP[j][1], u1);
            EX2_H2(aP[j][2], u2);
            EX2_H2(aP[j][3], u3);
        }

        #pragma unroll
        for (int ni = 0; ni < 8; ni++) {
            oacc[ni][0] *= c0; oacc[ni][1] *= c0;
            oacc[ni][2] *= c1; oacc[ni][3] *= c1;
        }
        lacc[0] *= c0; lacc[1] *= c0; lacc[2] *= c1; lacc[3] *= c1;

        #pragma unroll
        for (int j = 0; j < 4; j++)
            MMA_F16(lacc, aP[j][0],aP[j][1],aP[j][2],aP[j][3], ONES_H2, ONES_H2);

        #pragma unroll
        for (int j = 0; j < 4; j++) {
            #pragma unroll
            for (int np = 0; np < 4; np++) {
                uint32_t t0,t1,t2,t3;
                LDSM_X4T(t0,t1,t2,t3, vb_sm + voff + (uint32_t)(j * 16 * AQ_H + np * 16) * 2);
                MMA_F16(oacc[2*np],   aP[j][0],aP[j][1],aP[j][2],aP[j][3], t0,t1);
                MMA_F16(oacc[2*np+1], aP[j][0],aP[j][1],aP[j][2],aP[j][3], t2,t3);
            }
        }
        __syncthreads();
    }

    float i0 = 1.f / lacc[0], i1 = 1.f / lacc[2];
    #pragma unroll
    for (int ni = 0; ni < 8; ni++) {
        int c = hh*64 + ni*8 + 2*tg;
        size_t go = ((size_t)(b*SS + qt*128 + w*16 + g)) * DD + c;
        *(__half2*)(O + go)        = __floats2half2_rn(oacc[ni][0]*i0, oacc[ni][1]*i0);
        *(__half2*)(O + go + 8*DD) = __floats2half2_rn(oacc[ni][2]*i1, oacc[ni][3]*i1);
    }
}

// ======================= launcher ===========================================
extern "C" void kernel_launch(void* const* d_in, const int* in_sizes, int n_in,
                              void* d_out, int out_size)
{
    const float* x    = (const float*)d_in[0];
    const float* Wq   = (const float*)d_in[1];
    const float* Wk   = (const float*)d_in[2];
    const float* Wv   = (const float*)d_in[3];
    const float* Wo   = (const float*)d_in[4];
    const float* bo   = (const float*)d_in[5];
    const float* W1   = (const float*)d_in[6];
    const float* b1   = (const float*)d_in[7];
    const float* W2   = (const float*)d_in[8];
    const float* b2   = (const float*)d_in[9];
    const float* ln1s = (const float*)d_in[10];
    const float* ln1b = (const float*)d_in[11];
    const float* ln2s = (const float*)d_in[12];
    const float* ln2b = (const float*)d_in[13];
    float* out = (float*)d_out;

    __half *h,*qkv,*ctx,*ff,*wqkv,*wo,*w1,*w2;
    float *x1;
    cudaGetSymbolAddress((void**)&h,    g_h);
    cudaGetSymbolAddress((void**)&qkv,  g_qkv);
    cudaGetSymbolAddress((void**)&ctx,  g_ctx);
    cudaGetSymbolAddress((void**)&x1,   g_x1);
    cudaGetSymbolAddress((void**)&ff,   g_ff);
    cudaGetSymbolAddress((void**)&wqkv, g_wqkv);
    cudaGetSymbolAddress((void**)&wo,   g_wo);
    cudaGetSymbolAddress((void**)&w1,   g_w1);
    cudaGetSymbolAddress((void**)&w2,   g_w2);

    cudaFuncSetAttribute(tgemm<0,1>, cudaFuncAttributeMaxDynamicSharedMemorySize, GEMM_SMEM);
    cudaFuncSetAttribute(tgemm<1,0>, cudaFuncAttributeMaxDynamicSharedMemorySize, GEMM_SMEM);
    cudaFuncSetAttribute(tgemm<2,1>, cudaFuncAttributeMaxDynamicSharedMemorySize, GEMM_SMEM);
    cudaFuncSetAttribute(attn_kernel, cudaFuncAttributeMaxDynamicSharedMemorySize, ATT_SMEM);

    ln1_cvt_kernel<<<ROWS + CVT_BLOCKS, 256>>>(x, ln1s, ln1b, h,
                                               Wq, Wk, Wv, Wo, W1, W2,
                                               wqkv, wo, w1, w2);

    dim3 gQKV(QST/128, ROWS/128);  // (24, 64)
    dim3 gD  (DD/128,  ROWS/128);  // (8, 64)
    dim3 gFF (DFF/128, ROWS/128);  // (32, 64)

    tgemm<0,1><<<gQKV, 128, GEMM_SMEM>>>(h, wqkv, nullptr, nullptr, qkv, QST, DD);
    attn_kernel<<<dim3(SS/128, BB*HH), 256, ATT_SMEM>>>(qkv, ctx);
    tgemm<1,0><<<gD, 128, GEMM_SMEM>>>(ctx, wo, bo, x, x1, DD, DD);
    ln_kernel<<<ROWS, 256>>>(x1, ln2s, ln2b, h);
    tgemm<2,1><<<gFF, 128, GEMM_SMEM>>>(h, w1, b1, nullptr, ff, DFF, DD);
    tgemm<1,0><<<gD, 128, GEMM_SMEM>>>(ff, w2, b2, x1, out, DD, DFF);
}

// round 12
// speedup vs baseline: 2.2308x; 1.0426x over previous
#include <cuda_runtime.h>
#include <cuda_fp16.h>
#include <math.h>
#include <stdint.h>

#define BB   4
#define SS   2048
#define DD   1024
#define HH   16
#define HD   64
#define DFF  4096
#define ROWS (BB*SS)   // 8192
#define QST  (3*DD)    // qkv row stride

// ---------------- scratch (static device globals; no allocation) -----------
__device__ __half g_h   [ (size_t)ROWS*DD ];
__device__ __half g_qkv [ (size_t)ROWS*QST ];
__device__ __half g_ctx [ (size_t)ROWS*DD ];
__device__ float  g_x1  [ (size_t)ROWS*DD ];
__device__ __half g_ff  [ (size_t)ROWS*DFF ];
__device__ __half g_wqkv[ (size_t)DD*QST ];
__device__ __half g_wo  [ (size_t)DD*DD ];
__device__ __half g_w1  [ (size_t)DD*DFF ];
__device__ __half g_w2  [ (size_t)DFF*DD ];

// ======================= helpers ============================================
__device__ __forceinline__ uint32_t smem_u32(const void* p) {
    uint32_t a;
    asm("{ .reg .u64 t; cvta.to.shared.u64 t, %1; cvt.u32.u64 %0, t; }" : "=r"(a) : "l"(p));
    return a;
}
__device__ __forceinline__ void cp_async16(uint32_t dst, const void* src) {
    asm volatile("cp.async.cg.shared.global [%0], [%1], 16;" :: "r"(dst), "l"(src));
}
#define CP_COMMIT() asm volatile("cp.async.commit_group;")
#define CP_WAIT(N)  asm volatile("cp.async.wait_group %0;" :: "n"(N))

#define LDSM_X4(r0,r1,r2,r3, addr) \
    asm volatile("ldmatrix.sync.aligned.m8n8.x4.shared.b16 {%0,%1,%2,%3}, [%4];" \
        : "=r"(r0),"=r"(r1),"=r"(r2),"=r"(r3) : "r"(addr))
#define LDSM_X4T(r0,r1,r2,r3, addr) \
    asm volatile("ldmatrix.sync.aligned.m8n8.x4.trans.shared.b16 {%0,%1,%2,%3}, [%4];" \
        : "=r"(r0),"=r"(r1),"=r"(r2),"=r"(r3) : "r"(addr))

#define MMA_F16(acc, a0,a1,a2,a3, b0,b1) \
    asm volatile("mma.sync.aligned.m16n8k16.row.col.f32.f16.f16.f32 " \
        "{%0,%1,%2,%3}, {%4,%5,%6,%7}, {%8,%9}, {%0,%1,%2,%3};" \
        : "+f"((acc)[0]), "+f"((acc)[1]), "+f"((acc)[2]), "+f"((acc)[3]) \
        : "r"(a0), "r"(a1), "r"(a2), "r"(a3), "r"(b0), "r"(b1))

#define CVT_H2(d, hi, lo) \
    asm("cvt.rn.f16x2.f32 %0, %1, %2;" : "=r"(d) : "f"(hi), "f"(lo))
#define EX2_H2(d, a) \
    asm("ex2.approx.f16x2 %0, %1;" : "=r"(d) : "r"(a))

__device__ __forceinline__ float exp2_fast(float x) {
    float y;
    asm("ex2.approx.f32 %0, %1;" : "=f"(y) : "f"(x));
    return y;
}
__device__ __forceinline__ float tanh_fast(float x) {
    float y;
    asm("tanh.approx.f32 %0, %1;" : "=f"(y) : "f"(x));
    return y;
}
__device__ __forceinline__ float gelu_f(float x) {
    float u = 0.7978845608028654f * (x + 0.044715f * x * x * x);
    return 0.5f * x * (1.0f + tanh_fast(u));
}

// ========== fused: LN1 (blocks [0,ROWS)) + weight cvt (rest) ================
#define SEG (DD*DD/2)
#define SEGF (DD*DFF/2)
#define CVT_BLOCKS ((4*SEG + 2*SEGF)/256)    // 24576

__device__ __forceinline__ void ln_body(const float* __restrict__ xr,
                                        const float* __restrict__ scale,
                                        const float* __restrict__ shift,
                                        __half* __restrict__ orow)
{
    int t = threadIdx.x, wid = t >> 5, lane = t & 31;
    float v0 = xr[t], v1 = xr[t+256], v2 = xr[t+512], v3 = xr[t+768];
    float s  = v0+v1+v2+v3;
    float sq = v0*v0+v1*v1+v2*v2+v3*v3;
    #pragma unroll
    for (int off = 16; off > 0; off >>= 1) {
        s  += __shfl_xor_sync(0xffffffff, s,  off);
        sq += __shfl_xor_sync(0xffffffff, sq, off);
    }
    __shared__ float ws[2][8];
    if (lane == 0) { ws[0][wid] = s; ws[1][wid] = sq; }
    __syncthreads();
    float ts = 0.f, tsq = 0.f;
    #pragma unroll
    for (int i = 0; i < 8; i++) { ts += ws[0][i]; tsq += ws[1][i]; }
    float mean = ts * (1.0f/DD);
    float var  = tsq * (1.0f/DD) - mean*mean;
    float inv  = rsqrtf(var + 1e-8f);
    orow[t    ] = __float2half_rn(scale[t    ]*(v0-mean)*inv + shift[t    ]);
    orow[t+256] = __float2half_rn(scale[t+256]*(v1-mean)*inv + shift[t+256]);
    orow[t+512] = __float2half_rn(scale[t+512]*(v2-mean)*inv + shift[t+512]);
    orow[t+768] = __float2half_rn(scale[t+768]*(v3-mean)*inv + shift[t+768]);
}

__global__ __launch_bounds__(256)
void ln1_cvt_kernel(const float* __restrict__ x,
                    const float* __restrict__ ln1s, const float* __restrict__ ln1b,
                    __half* __restrict__ h,
                    const float* __restrict__ Wq, const float* __restrict__ Wk,
                    const float* __restrict__ Wv, const float* __restrict__ Wo,
                    const float* __restrict__ W1, const float* __restrict__ W2,
                    __half* __restrict__ wqkv, __half* __restrict__ wo,
                    __half* __restrict__ w1,   __half* __restrict__ w2)
{
    int bid = blockIdx.x;
    if (bid < ROWS) {
        ln_body(x + (size_t)bid * DD, ln1s, ln1b, h + (size_t)bid * DD);
        return;
    }
    int i = (bid - ROWS) * 256 + threadIdx.x;
    const float2* src;
    __half2* dst;
    if (i < 3*SEG) {
        int s = i / SEG, j = i - s * SEG;
        src = (const float2*)(s == 0 ? Wq : s == 1 ? Wk : Wv) + j;
        int r = j / (DD/2), c = j - r * (DD/2);
        dst = (__half2*)wqkv + (size_t)r * (QST/2) + s * (DD/2) + c;
    } else if (i < 4*SEG) {
        int j = i - 3*SEG;
        src = (const float2*)Wo + j;  dst = (__half2*)wo + j;
    } else if (i < 4*SEG + SEGF) {
        int j = i - 4*SEG;
        src = (const float2*)W1 + j;  dst = (__half2*)w1 + j;
    } else {
        int j = i - 4*SEG - SEGF;
        src = (const float2*)W2 + j;  dst = (__half2*)w2 + j;
    }
    float2 v = *src;
    *dst = __floats2half2_rn(v.x, v.y);
}

// plain LN kernel (for LN2)
__global__ __launch_bounds__(256)
void ln_kernel(const float* __restrict__ x, const float* __restrict__ scale,
               const float* __restrict__ shift, __half* __restrict__ out)
{
    int row = blockIdx.x;
    ln_body(x + (size_t)row * DD, scale, shift, out + (size_t)row * DD);
}

// ====== fp16 mma GEMM, BK=32, 4-stage cp.async, single sync per chunk =======
// 128 thr = 4 warps (2m x 2n), CTA tile 128x128, warp tile 64x64, occupancy 2.
#define AS_H 40
#define BS_H 136
#define SA_BYTES (128*AS_H*2)
#define SB_BYTES (32*BS_H*2)
#define STG_BYTES (SA_BYTES+SB_BYTES)    // 18944
#define GEMM_SMEM (4*STG_BYTES)          // 75776

template<int EPI, int OUTH>
__global__ __launch_bounds__(128, 2)
void tgemm(const __half* __restrict__ A, const __half* __restrict__ W,
           const float* __restrict__ bias, const float* __restrict__ res,
           void* __restrict__ C, int N, int K)
{
    extern __shared__ char smem[];
    const uint32_t sb = smem_u32(smem);
    const int tid  = threadIdx.x;
    const int wid  = tid >> 5, lane = tid & 31;
    const int g    = lane >> 2, tg = lane & 3;
    const int wm   = (wid >> 1) * 64, wn = (wid & 1) * 64;
    const int brow = blockIdx.y * 128, bcol = blockIdx.x * 128;

    float acc[4][8][4];
    #pragma unroll
    for (int mi=0;mi<4;mi++)
        #pragma unroll
        for (int ni=0;ni<8;ni++)
            #pragma unroll
            for (int e=0;e<4;e++) acc[mi][ni][e]=0.f;

    auto stage = [&](int c, int buf) {
        uint32_t base = sb + buf * STG_BYTES;
        int k0 = c * 32;
        #pragma unroll
        for (int it = 0; it < 4; it++) {
            int idx = it * 128 + tid;
            int row = idx >> 2, c8 = (idx & 3) * 8;
            cp_async16(base + (uint32_t)(row * AS_H + c8) * 2,
                       A + (size_t)(brow + row) * K + k0 + c8);
        }
        #pragma unroll
        for (int it = 0; it < 4; it++) {
            int idx = it * 128 + tid;
            int row = idx >> 4, c8 = (idx & 15) * 8;
            cp_async16(base + SA_BYTES + (uint32_t)(row * BS_H + c8) * 2,
                       W + (size_t)(k0 + row) * N + bcol + c8);
        }
        CP_COMMIT();
    };

    const uint32_t aoff = (uint32_t)((wm + (lane & 15)) * AS_H + 8 * (lane >> 4)) * 2;
    const uint32_t boff = (uint32_t)(((lane & 7) + 8 * ((lane >> 3) & 1)) * BS_H
                                     + wn + 8 * (lane >> 4)) * 2;

    const int nch = K / 32;
    stage(0, 0);
    stage(1, 1);
    stage(2, 2);
    for (int c = 0; c < nch; c++) {
        CP_WAIT(2);          // pending {c, c+1, c+2} -> chunk c complete
        __syncthreads();     // chunk c visible; all warps done reading buf (c+3)%4
        if (c + 3 < nch) stage(c + 3, (c + 3) & 3);
        else             CP_COMMIT();   // keep group count constant for the tail
        uint32_t sbuf = sb + (c & 3) * STG_BYTES;

        #pragma unroll
        for (int kb = 0; kb < 32; kb += 16) {
            uint32_t a[4][4];
            #pragma unroll
            for (int mi = 0; mi < 4; mi++)
                LDSM_X4(a[mi][0], a[mi][1], a[mi][2], a[mi][3],
                        sbuf + aoff + (uint32_t)(mi * 16 * AS_H + kb) * 2);
            #pragma unroll
            for (int np = 0; np < 4; np++) {
                uint32_t t0,t1,t2,t3;
                LDSM_X4T(t0,t1,t2,t3,
                         sbuf + SA_BYTES + boff + (uint32_t)(kb * BS_H + np * 16) * 2);
                #pragma unroll
                for (int mi = 0; mi < 4; mi++) {
                    MMA_F16(acc[mi][2*np],   a[mi][0],a[mi][1],a[mi][2],a[mi][3], t0,t1);
                    MMA_F16(acc[mi][2*np+1], a[mi][0],a[mi][1],a[mi][2],a[mi][3], t2,t3);
                }
            }
        }
    }

    #pragma unroll
    for (int mi = 0; mi < 4; mi++) {
        int r0 = brow + wm + mi * 16 + g;
        #pragma unroll
        for (int ni = 0; ni < 8; ni++) {
            int c = bcol + wn + ni * 8 + 2 * tg;
            float v0 = acc[mi][ni][0], v1 = acc[mi][ni][1];
            float v2 = acc[mi][ni][2], v3 = acc[mi][ni][3];
            if (EPI == 1) {
                float b0 = bias[c], b1 = bias[c+1];
                const float* R0 = res + (size_t)r0 * N + c;
                const float* R1 = res + (size_t)(r0+8) * N + c;
                v0 += b0 + R0[0]; v1 += b1 + R0[1];
                v2 += b0 + R1[0]; v3 += b1 + R1[1];
            }
            if (EPI == 2) {
                float b0 = bias[c], b1 = bias[c+1];
                v0 = gelu_f(v0 + b0); v1 = gelu_f(v1 + b1);
                v2 = gelu_f(v2 + b0); v3 = gelu_f(v3 + b1);
            }
            if (OUTH) {
                __half* Ch = (__half*)C;
                *(__half2*)(Ch + (size_t)r0 * N + c)     = __floats2half2_rn(v0, v1);
                *(__half2*)(Ch + (size_t)(r0+8) * N + c) = __floats2half2_rn(v2, v3);
            } else {
                float* Cf = (float*)C;
                *(float2*)(Cf + (size_t)r0 * N + c)     = make_float2(v0, v1);
                *(float2*)(Cf + (size_t)(r0+8) * N + c) = make_float2(v2, v3);
            }
        }
    }
}

// ===== fp16 tensor-core causal flash attention, 3-buffer KV pipeline ========
#define AQ_H 72
#define ATT_Q_OFF 0
#define ATT_K_OFF (128*AQ_H)
#define ATT_V_OFF (ATT_K_OFF + 3*64*AQ_H)
#define ATT_SMEM  ((ATT_V_OFF + 3*64*AQ_H)*2)   // 73728 bytes
#define SCL2 (0.125f * 1.44269504088896f)
#define ONES_H2 0x3C003C00u

__global__ __launch_bounds__(256, 2)
void attn_kernel(const __half* __restrict__ QKV, __half* __restrict__ O)
{
    extern __shared__ __half sh[];
    const uint32_t sb = smem_u32(sh);

    const int qt = (int)gridDim.x - 1 - (int)blockIdx.x;   // heavy-first
    const int bh = blockIdx.y;
    const int b = bh >> 4, hh = bh & 15;
    const int tid = threadIdx.x, w = tid >> 5, lane = tid & 31;
    const int g = lane >> 2, tg = lane & 3;

    {   // Q tile (joins cp.async group 0, committed by loadKV(0,0))
        const __half* Qg = QKV + ((size_t)(b*SS + qt*128))*QST + hh*64;
        #pragma unroll
        for (int it = 0; it < 4; it++) {
            int idx = it * 256 + tid;
            int row = idx >> 3, c8 = (idx & 7) * 8;
            cp_async16(sb + (uint32_t)(ATT_Q_OFF + row * AQ_H + c8) * 2,
                       Qg + (size_t)row * QST + c8);
        }
    }
    auto loadKV = [&](int kt, int buf) {
        const __half* Kg = QKV + ((size_t)(b*SS + kt*64))*QST + DD   + hh*64;
        const __half* Vg = QKV + ((size_t)(b*SS + kt*64))*QST + 2*DD + hh*64;
        uint32_t kbase = sb + (uint32_t)(ATT_K_OFF + buf * 64 * AQ_H) * 2;
        uint32_t vbase = sb + (uint32_t)(ATT_V_OFF + buf * 64 * AQ_H) * 2;
        #pragma unroll
        for (int it = 0; it < 2; it++) {
            int idx = it * 256 + tid;
            int row = idx >> 3, c8 = (idx & 7) * 8;
            cp_async16(kbase + (uint32_t)(row * AQ_H + c8) * 2, Kg + (size_t)row * QST + c8);
            cp_async16(vbase + (uint32_t)(row * AQ_H + c8) * 2, Vg + (size_t)row * QST + c8);
        }
        CP_COMMIT();
    };

    float oacc[8][4];
    #pragma unroll
    for (int ni=0;ni<8;ni++)
        #pragma unroll
        for (int e=0;e<4;e++) oacc[ni][e]=0.f;
    float lacc[4] = {0.f, 0.f, 0.f, 0.f};
    float m0 = -INFINITY, m1 = -INFINITY;

    const uint32_t qoff = (uint32_t)((w*16 + (lane & 15)) * AQ_H + 8 * (lane >> 4)) * 2;
    const uint32_t koff = (uint32_t)(((lane & 7) + 8 * (lane >> 4)) * AQ_H
                                     + 8 * ((lane >> 3) & 1)) * 2;
    const uint32_t voff = (uint32_t)(((lane & 7) + 8 * ((lane >> 3) & 1)) * AQ_H
                                     + 8 * (lane >> 4)) * 2;

    const int nkt = 2 * qt + 2;      // >= 2 always
    loadKV(0, 0);
    loadKV(1, 1);
    for (int kt = 0; kt < nkt; kt++) {
        CP_WAIT(1);          // pending {kt, kt+1} -> group kt complete
        __syncthreads();     // tile kt visible; all warps done with buf (kt+2)%3
        if (kt + 2 < nkt) loadKV(kt + 2, (kt + 2) % 3);
        else              CP_COMMIT();

        int buf = kt % 3;
        uint32_t kb_sm = sb + (uint32_t)(ATT_K_OFF + buf * 64 * AQ_H) * 2;
        uint32_t vb_sm = sb + (uint32_t)(ATT_V_OFF + buf * 64 * AQ_H) * 2;

        float sacc[8][4];
        #pragma unroll
        for (int ni=0;ni<8;ni++)
            #pragma unroll
            for (int e=0;e<4;e++) sacc[ni][e]=0.f;

        #pragma unroll
        for (int kb = 0; kb < 64; kb += 16) {
            uint32_t a0,a1,a2,a3;
            LDSM_X4(a0,a1,a2,a3, sb + (uint32_t)(ATT_Q_OFF)*2 + qoff + (uint32_t)kb * 2);
            #pragma unroll
            for (int np = 0; np < 4; np++) {
                uint32_t t0,t1,t2,t3;
                LDSM_X4(t0,t1,t2,t3, kb_sm + koff + (uint32_t)(np * 16 * AQ_H + kb) * 2);
                MMA_F16(sacc[2*np],   a0,a1,a2,a3, t0,t1);
                MMA_F16(sacc[2*np+1], a0,a1,a2,a3, t2,t3);
            }
        }

        const bool needMask = (kt * 64 + 63) > (qt*128 + w*16);
        if (needMask) {
            const int qg0 = qt*128 + w*16 + g, qg1 = qg0 + 8;
            #pragma unroll
            for (int ni = 0; ni < 8; ni++) {
                int key0 = kt*64 + ni*8 + 2*tg;
                #pragma unroll
                for (int e = 0; e < 4; e++) {
                    int key = key0 + (e & 1);
                    int qr  = (e >= 2) ? qg1 : qg0;
                    if (key > qr) sacc[ni][e] = -INFINITY;
                }
            }
        }

        float rx0 = -INFINITY, rx1 = -INFINITY;
        #pragma unroll
        for (int ni = 0; ni < 8; ni++) {
            rx0 = fmaxf(rx0, fmaxf(sacc[ni][0], sacc[ni][1]));
            rx1 = fmaxf(rx1, fmaxf(sacc[ni][2], sacc[ni][3]));
        }
        rx0 = fmaxf(rx0, __shfl_xor_sync(0xffffffff, rx0, 1));
        rx0 = fmaxf(rx0, __shfl_xor_sync(0xffffffff, rx0, 2));
        rx1 = fmaxf(rx1, __shfl_xor_sync(0xffffffff, rx1, 1));
        rx1 = fmaxf(rx1, __shfl_xor_sync(0xffffffff, rx1, 2));
        float mn0 = fmaxf(m0, rx0 * SCL2), mn1 = fmaxf(m1, rx1 * SCL2);
        float c0 = exp2_fast(m0 - mn0), c1 = exp2_fast(m1 - mn1);
        float nm0 = -mn0, nm1 = -mn1;
        m0 = mn0;  m1 = mn1;

        uint32_t aP[4][4];
        #pragma unroll
        for (int j = 0; j < 4; j++) {
            int n0 = 2*j, n1 = 2*j + 1;
            float d00 = fmaf(sacc[n0][0], SCL2, nm0);
            float d01 = fmaf(sacc[n0][1], SCL2, nm0);
            float d02 = fmaf(sacc[n0][2], SCL2, nm1);
            float d03 = fmaf(sacc[n0][3], SCL2, nm1);
            float d10 = fmaf(sacc[n1][0], SCL2, nm0);
            float d11 = fmaf(sacc[n1][1], SCL2, nm0);
            float d12 = fmaf(sacc[n1][2], SCL2, nm1);
            float d13 = fmaf(sacc[n1][3], SCL2, nm1);
            uint32_t u0, u1, u2, u3;
            CVT_H2(u0, d01, d00);
            CVT_H2(u1, d03, d02);
            CVT_H2(u2, d11, d10);
            CVT_H2(u3, d13, d12);
            EX2_H2(aP[j][0], u0);
            EX2_H2(aP[j][1], u1);
            EX2_H2(aP[j][2], u2);
            EX2_H2(aP[j][3], u3);
        }

        #pragma unroll
        for (int ni = 0; ni < 8; ni++) {
            oacc[ni][0] *= c0; oacc[ni][1] *= c0;
            oacc[ni][2] *= c1; oacc[ni][3] *= c1;
        }
        lacc[0] *= c0; lacc[1] *= c0; lacc[2] *= c1; lacc[3] *= c1;

        #pragma unroll
        for (int j = 0; j < 4; j++)
            MMA_F16(lacc, aP[j][0],aP[j][1],aP[j][2],aP[j][3], ONES_H2, ONES_H2);

        #pragma unroll
        for (int j = 0; j < 4; j++) {
            #pragma unroll
            for (int np = 0; np < 4; np++) {
                uint32_t t0,t1,t2,t3;
                LDSM_X4T(t0,t1,t2,t3, vb_sm + voff + (uint32_t)(j * 16 * AQ_H + np * 16) * 2);
                MMA_F16(oacc[2*np],   aP[j][0],aP[j][1],aP[j][2],aP[j][3], t0,t1);
                MMA_F16(oacc[2*np+1], aP[j][0],aP[j][1],aP[j][2],aP[j][3], t2,t3);
            }
        }
    }

    float i0 = 1.f / lacc[0], i1 = 1.f / lacc[2];
    #pragma unroll
    for (int ni = 0; ni < 8; ni++) {
        int c = hh*64 + ni*8 + 2*tg;
        size_t go = ((size_t)(b*SS + qt*128 + w*16 + g)) * DD + c;
        *(__half2*)(O + go)        = __floats2half2_rn(oacc[ni][0]*i0, oacc[ni][1]*i0);
        *(__half2*)(O + go + 8*DD) = __floats2half2_rn(oacc[ni][2]*i1, oacc[ni][3]*i1);
    }
}

// ======================= launcher ===========================================
extern "C" void kernel_launch(void* const* d_in, const int* in_sizes, int n_in,
                              void* d_out, int out_size)
{
    const float* x    = (const float*)d_in[0];
    const float* Wq   = (const float*)d_in[1];
    const float* Wk   = (const float*)d_in[2];
    const float* Wv   = (const float*)d_in[3];
    const float* Wo   = (const float*)d_in[4];
    const float* bo   = (const float*)d_in[5];
    const float* W1   = (const float*)d_in[6];
    const float* b1   = (const float*)d_in[7];
    const float* W2   = (const float*)d_in[8];
    const float* b2   = (const float*)d_in[9];
    const float* ln1s = (const float*)d_in[10];
    const float* ln1b = (const float*)d_in[11];
    const float* ln2s = (const float*)d_in[12];
    const float* ln2b = (const float*)d_in[13];
    float* out = (float*)d_out;

    __half *h,*qkv,*ctx,*ff,*wqkv,*wo,*w1,*w2;
    float *x1;
    cudaGetSymbolAddress((void**)&h,    g_h);
    cudaGetSymbolAddress((void**)&qkv,  g_qkv);
    cudaGetSymbolAddress((void**)&ctx,  g_ctx);
    cudaGetSymbolAddress((void**)&x1,   g_x1);
    cudaGetSymbolAddress((void**)&ff,   g_ff);
    cudaGetSymbolAddress((void**)&wqkv, g_wqkv);
    cudaGetSymbolAddress((void**)&wo,   g_wo);
    cudaGetSymbolAddress((void**)&w1,   g_w1);
    cudaGetSymbolAddress((void**)&w2,   g_w2);

    cudaFuncSetAttribute(tgemm<0,1>, cudaFuncAttributeMaxDynamicSharedMemorySize, GEMM_SMEM);
    cudaFuncSetAttribute(tgemm<1,0>, cudaFuncAttributeMaxDynamicSharedMemorySize, GEMM_SMEM);
    cudaFuncSetAttribute(tgemm<2,1>, cudaFuncAttributeMaxDynamicSharedMemorySize, GEMM_SMEM);
    cudaFuncSetAttribute(attn_kernel, cudaFuncAttributeMaxDynamicSharedMemorySize, ATT_SMEM);

    ln1_cvt_kernel<<<ROWS + CVT_BLOCKS, 256>>>(x, ln1s, ln1b, h,
                                               Wq, Wk, Wv, Wo, W1, W2,
                                               wqkv, wo, w1, w2);

    dim3 gQKV(QST/128, ROWS/128);  // (24, 64)
    dim3 gD  (DD/128,  ROWS/128);  // (8, 64)
    dim3 gFF (DFF/128, ROWS/128);  // (32, 64)

    tgemm<0,1><<<gQKV, 128, GEMM_SMEM>>>(h, wqkv, nullptr, nullptr, qkv, QST, DD);
    attn_kernel<<<dim3(SS/128, BB*HH), 256, ATT_SMEM>>>(qkv, ctx);
    tgemm<1,0><<<gD, 128, GEMM_SMEM>>>(ctx, wo, bo, x, x1, DD, DD);
    ln_kernel<<<ROWS, 256>>>(x1, ln2s, ln2b, h);
    tgemm<2,1><<<gFF, 128, GEMM_SMEM>>>(h, w1, b1, nullptr, ff, DFF, DD);
    tgemm<1,0><<<gD, 128, GEMM_SMEM>>>(ff, w2, b2, x1, out, DD, DFF);
}